// round 14
// baseline (speedup 1.0000x reference)
#include <cuda_runtime.h>
#include <cuda_fp16.h>
#include <mma.h>
#include <cstdint>
using namespace nvcuda;

#define Nn 50000
#define Ee 800000
#define Hh 4
#define Dd 128
#define HDd 512
#define Ll 4

#define WSZ (Dd * HDd)          // 65536 per weight matrix
#define NWEIGHT (3 * Ll * WSZ)  // 786432
#define NFEAT (Nn * Dd)         // 6.4M

// gemm_h (dual) smem, BK=32, 3-stage (halves): 3 A bufs (128x40) + 3 B bufs (32x136)
#define ASTRIDE_H 5120          // 128*40
#define BBASE_H   15360         // 3*ASTRIDE_H
#define BSTRIDE_H 4352          // 32*136
#define SMBYTES_H ((BBASE_H + 3 * BSTRIDE_H) * 2)   // 56832 B (dynamic)

// gemm_ln smem, BK=32, 3-stage: 3 A bufs (64x40) + 3 B bufs (32x136) = 41472 B static
#define LN_ASTRIDE 2560         // 64*40
#define LN_BBASE   7680         // 3*LN_ASTRIDE
#define LN_SMBYTES ((LN_BBASE + 3 * BSTRIDE_H) * 2) // 41472

#define GRID_H  592             // persistent grid for gemm_h (2 CTAs/SM x 148... x2)
#define GRID_LN 296             // persistent grid for gemm_ln

// ---------------- scratch (static device memory; no allocations) ----------------
__device__ __align__(16) __half g_featH[(size_t)Nn * HDd];  // fp16 feat (k_agg payload)
__device__ __align__(16) __half g_resR [(size_t)Nn * HDd];  // fp16 x@Wr (k_agg residual)
__device__ __align__(16) __half g_resH [(size_t)Nn * HDd];  // fp16 k_agg out (GEMM2 A)
__device__ __align__(16) float  g_el[Nn * Hh];
__device__ __align__(16) float  g_er[Nn * Hh];
__device__ __align__(16) __half g_xh0[(size_t)Nn * Dd];     // fp16 features
__device__ __align__(16) __half g_xhA[(size_t)Nn * Dd];
__device__ __align__(16) __half g_xhB[(size_t)Nn * Dd];
__device__ __align__(16) __half g_wh[NWEIGHT];              // fp16 weights
__device__ int g_deg[Nn];
__device__ int g_rowptr[Nn + 1];
__device__ int g_cursor[Nn];
__device__ int g_csrsrc[Ee];

// ---------------- preamble: convert weights+features to fp16, zero deg -------------
__global__ void k_pre(const float* __restrict__ Wf, const float* __restrict__ Wr,
                      const float* __restrict__ Wn, const float* __restrict__ feats)
{
    int i = blockIdx.x * blockDim.x + threadIdx.x;
    if (i < NFEAT) g_xh0[i] = __float2half_rn(feats[i]);
    if (i < Ll * WSZ) {
        g_wh[i]                = __float2half_rn(Wf[i]);
        g_wh[Ll * WSZ + i]     = __float2half_rn(Wr[i]);
        g_wh[2 * Ll * WSZ + i] = __float2half_rn(Wn[i]);
    }
    if (i < Nn) g_deg[i] = 0;
}

__global__ void k_count(const int* __restrict__ dst) {
    int i = blockIdx.x * blockDim.x + threadIdx.x;
    if (i < Ee) atomicAdd(&g_deg[dst[i]], 1);
}

// single-block warp-shuffle scan: 4 elems/thread, 4096/chunk, carry across chunks
__global__ void k_scan() {
    __shared__ int wsum[32];
    __shared__ int carry;
    int t = threadIdx.x, lane = t & 31, wid = t >> 5;
    if (t == 0) { carry = 0; g_rowptr[0] = 0; }
    __syncthreads();
    for (int base = 0; base < Nn; base += 4096) {
        int idx = base + t * 4;
        int v0 = (idx + 0 < Nn) ? g_deg[idx + 0] : 0;
        int v1 = (idx + 1 < Nn) ? g_deg[idx + 1] : 0;
        int v2 = (idx + 2 < Nn) ? g_deg[idx + 2] : 0;
        int v3 = (idx + 3 < Nn) ? g_deg[idx + 3] : 0;
        int s0 = v0, s1 = s0 + v1, s2 = s1 + v2, s3 = s2 + v3;
        int incl = s3;
        #pragma unroll
        for (int o = 1; o < 32; o <<= 1) {
            int x = __shfl_up_sync(0xffffffffu, incl, o);
            if (lane >= o) incl += x;
        }
        if (lane == 31) wsum[wid] = incl;
        __syncthreads();
        if (wid == 0) {
            int x = wsum[lane];
            #pragma unroll
            for (int o = 1; o < 32; o <<= 1) {
                int y = __shfl_up_sync(0xffffffffu, x, o);
                if (lane >= o) x += y;
            }
            wsum[lane] = x;
        }
        __syncthreads();
        int pre = carry + (wid ? wsum[wid - 1] : 0) + (incl - s3);
        if (idx + 0 < Nn) { g_rowptr[idx + 1] = pre + s0; g_cursor[idx + 0] = pre; }
        if (idx + 1 < Nn) { g_rowptr[idx + 2] = pre + s1; g_cursor[idx + 1] = pre + s0; }
        if (idx + 2 < Nn) { g_rowptr[idx + 3] = pre + s2; g_cursor[idx + 2] = pre + s1; }
        if (idx + 3 < Nn) { g_rowptr[idx + 4] = pre + s3; g_cursor[idx + 3] = pre + s2; }
        __syncthreads();
        if (t == 0) carry += wsum[31];
        __syncthreads();
    }
}

__global__ void k_fill(const int* __restrict__ src, const int* __restrict__ dst) {
    int i = blockIdx.x * blockDim.x + threadIdx.x;
    if (i < Ee) {
        int p = atomicAdd(&g_cursor[dst[i]], 1);
        g_csrsrc[p] = src[i];
    }
}

// ---------------- cp.async helper ----------------
__device__ __forceinline__ void cp16(uint32_t dst, const void* src, bool pred) {
    int sz = pred ? 16 : 0;
    asm volatile("cp.async.cg.shared.global [%0], [%1], 16, %2;\n"
                 :: "r"(dst), "l"(src), "r"(sz));
}

__device__ __forceinline__ uint2 pack_h4(float x, float y, float z, float w) {
    __half2 h0 = __floats2half2_rn(x, y);
    __half2 h1 = __floats2half2_rn(z, w);
    uint2 u;
    u.x = *reinterpret_cast<unsigned*>(&h0);
    u.y = *reinterpret_cast<unsigned*>(&h1);
    return u;
}

// ---------------- dual fp16 GEMM, CTA 128x128, BK=32, 3-stage, persistent ---------
// Grid-stride over (2*TPH x gy) tiles. Both halves epilogue via smem -> fp16.
// feat half (bx<TPH): also computes attn el/er (head h == bx).
template<int K, int TPH>
__global__ __launch_bounds__(256) void gemm_h(
    const __half* __restrict__ A,
    const __half* __restrict__ B0, const __half* __restrict__ B1,
    int M, const float* __restrict__ p0, const float* __restrict__ p1)
{
    constexpr int NN = TPH * 128;
    extern __shared__ __half smh[];
    float* smf = reinterpret_cast<float*>(smh);

    const int tid = threadIdx.x;
    const int warp = tid >> 5;
    const int lane = tid & 31;
    const int wm = warp & 1, wn = warp >> 1;

    const int gy = (M + 127) >> 7;
    const int total = 2 * TPH * gy;

    for (int rb = blockIdx.x; rb < total; rb += gridDim.x) {
        const int row0 = (rb / (2 * TPH)) * 128;
        int bx = rb % (2 * TPH);
        bool isFeatHalf = (bx < TPH);
        const __half* B = B0;
        if (!isFeatHalf) { bx -= TPH; B = B1; }
        const int col0 = bx * 128;

        wmma::fragment<wmma::accumulator, 16, 16, 16, float> acc[4][2];
        #pragma unroll
        for (int i = 0; i < 4; i++)
            #pragma unroll
            for (int j = 0; j < 2; j++)
                wmma::fill_fragment(acc[i][j], 0.0f);

        constexpr int KT = K >> 5;   // BK=32

        auto stage = [&](int buf, int k0) {
            __half* As = smh + buf * ASTRIDE_H;
            __half* Bs = smh + BBASE_H + buf * BSTRIDE_H;
            #pragma unroll
            for (int p = 0; p < 2; p++) {   // A: 128 rows x 32 halves
                int c = tid + p * 256;
                int r = c >> 2, q = c & 3;
                int gm = row0 + r;
                const __half* srcp = A + (size_t)gm * K + k0 + q * 8;
                uint32_t d = (uint32_t)__cvta_generic_to_shared(&As[r * 40 + q * 8]);
                cp16(d, srcp, gm < M);
            }
            #pragma unroll
            for (int p = 0; p < 2; p++) {   // B: 32 rows x 128 halves
                int c = tid + p * 256;
                int r = c >> 4, q = c & 15;
                const __half* srcp = B + (size_t)(k0 + r) * NN + col0 + q * 8;
                uint32_t d = (uint32_t)__cvta_generic_to_shared(&Bs[r * 136 + q * 8]);
                cp16(d, srcp, true);
            }
            asm volatile("cp.async.commit_group;");
        };

        stage(0, 0);
        stage(1, 32);

        #pragma unroll
        for (int kt = 0; kt < KT; kt++) {
            if (kt + 2 < KT) asm volatile("cp.async.wait_group 1;");
            else             asm volatile("cp.async.wait_group 0;");
            __syncthreads();

            const int buf = kt % 3;
            const __half* As = smh + buf * ASTRIDE_H;
            const __half* Bs = smh + BBASE_H + buf * BSTRIDE_H;
            #pragma unroll
            for (int kk = 0; kk < 2; kk++) {
                wmma::fragment<wmma::matrix_a, 16, 16, 16, __half, wmma::row_major> a[4];
                wmma::fragment<wmma::matrix_b, 16, 16, 16, __half, wmma::row_major> b[2];
                #pragma unroll
                for (int i = 0; i < 4; i++)
                    wmma::load_matrix_sync(a[i], As + (wm * 64 + i * 16) * 40 + kk * 16, 40);
                #pragma unroll
                for (int j = 0; j < 2; j++)
                    wmma::load_matrix_sync(b[j], Bs + (kk * 16) * 136 + wn * 32 + j * 16, 136);
                #pragma unroll
                for (int i = 0; i < 4; i++)
                    #pragma unroll
                    for (int j = 0; j < 2; j++)
                        wmma::mma_sync(acc[i][j], a[i], b[j], acc[i][j]);
            }

            if (kt + 2 < KT) stage((kt + 2) % 3, (kt + 2) << 5);
        }

        // epilogue: acc -> smem (two 64-row phases) -> fp16 global (+ el/er feat half)
        float* sC = smf;   // 64 x 132 floats
        float4 alv, arv;
        if (isFeatHalf) {
            alv = *(const float4*)(p0 + col0 + lane * 4);
            arv = *(const float4*)(p1 + col0 + lane * 4);
        }
        __half* outbase = isFeatHalf ? g_featH : g_resR;
        __syncthreads();
        #pragma unroll
        for (int p = 0; p < 2; p++) {
            if (wm == p) {
                #pragma unroll
                for (int i = 0; i < 4; i++)
                    #pragma unroll
                    for (int j = 0; j < 2; j++)
                        wmma::store_matrix_sync(
                            sC + (size_t)(i * 16) * 132 + wn * 32 + j * 16,
                            acc[i][j], 132, wmma::mem_row_major);
            }
            __syncthreads();
            #pragma unroll
            for (int rr = 0; rr < 8; rr++) {
                int lr = warp * 8 + rr;
                int gm = row0 + p * 64 + lr;
                float4 v = *(const float4*)(sC + (size_t)lr * 132 + lane * 4);
                bool valid = gm < M;
                if (valid) {
                    uint2 u = pack_h4(v.x, v.y, v.z, v.w);
                    *(uint2*)(outbase + (size_t)gm * HDd + col0 + lane * 4) = u;
                }
                if (isFeatHalf) {
                    float sl = v.x * alv.x + v.y * alv.y + v.z * alv.z + v.w * alv.w;
                    float sr = v.x * arv.x + v.y * arv.y + v.z * arv.z + v.w * arv.w;
                    #pragma unroll
                    for (int o = 16; o; o >>= 1) {
                        sl += __shfl_xor_sync(0xffffffffu, sl, o);
                        sr += __shfl_xor_sync(0xffffffffu, sr, o);
                    }
                    if (lane == 0 && valid) {
                        g_el[gm * Hh + bx] = sl;
                        g_er[gm * Hh + bx] = sr;
                    }
                }
            }
            __syncthreads();
        }
    }
}

// ---------------- GEMM2 + LN: CTA 64x128, BK=32, 3-stage, persistent --------------
template<int K>
__global__ __launch_bounds__(256) void gemm_ln(
    const __half* __restrict__ A, const __half* __restrict__ B,
    float* __restrict__ C0, __half* __restrict__ CH, int M,
    const float* __restrict__ bn, const float* __restrict__ lng,
    const float* __restrict__ lnb, int doHalf)
{
    constexpr int NN = 128;
    __shared__ __align__(16) char smraw[LN_SMBYTES];
    __half* smh = reinterpret_cast<__half*>(smraw);
    float* smf = reinterpret_cast<float*>(smraw);

    const int tid = threadIdx.x;
    const int warp = tid >> 5;
    const int lane = tid & 31;
    const int wm = warp & 1, wn = warp >> 1;

    float4 bnv = ((const float4*)bn)[lane];
    float4 ggv = ((const float4*)lng)[lane];
    float4 bbv = ((const float4*)lnb)[lane];

    const int total = (M + 63) >> 6;

    for (int rb = blockIdx.x; rb < total; rb += gridDim.x) {
        const int row0 = rb * 64;

        wmma::fragment<wmma::accumulator, 16, 16, 16, float> acc[2][2];
        #pragma unroll
        for (int i = 0; i < 2; i++)
            #pragma unroll
            for (int j = 0; j < 2; j++)
                wmma::fill_fragment(acc[i][j], 0.0f);

        constexpr int KT = K >> 5;

        auto stage = [&](int buf, int k0) {
            __half* As = smh + buf * LN_ASTRIDE;
            __half* Bs = smh + LN_BBASE + buf * BSTRIDE_H;
            {   // A: 64 rows x 32 halves = 256 x 16B (1/thread)
                int r = tid >> 2, q = tid & 3;
                int gm = row0 + r;
                const __half* srcp = A + (size_t)gm * K + k0 + q * 8;
                uint32_t d = (uint32_t)__cvta_generic_to_shared(&As[r * 40 + q * 8]);
                cp16(d, srcp, gm < M);
            }
            #pragma unroll
            for (int p = 0; p < 2; p++) {   // B: 32 rows x 128 halves
                int c = tid + p * 256;
                int r = c >> 4, q = c & 15;
                const __half* srcp = B + (size_t)(k0 + r) * NN + q * 8;
                uint32_t d = (uint32_t)__cvta_generic_to_shared(&Bs[r * 136 + q * 8]);
                cp16(d, srcp, true);
            }
            asm volatile("cp.async.commit_group;");
        };

        stage(0, 0);
        stage(1, 32);

        #pragma unroll
        for (int kt = 0; kt < KT; kt++) {
            if (kt + 2 < KT) asm volatile("cp.async.wait_group 1;");
            else             asm volatile("cp.async.wait_group 0;");
            __syncthreads();

            const int buf = kt % 3;
            const __half* As = smh + buf * LN_ASTRIDE;
            const __half* Bs = smh + LN_BBASE + buf * BSTRIDE_H;
            #pragma unroll
            for (int kk = 0; kk < 2; kk++) {
                wmma::fragment<wmma::matrix_a, 16, 16, 16, __half, wmma::row_major> a[2];
                wmma::fragment<wmma::matrix_b, 16, 16, 16, __half, wmma::row_major> b[2];
                #pragma unroll
                for (int i = 0; i < 2; i++)
                    wmma::load_matrix_sync(a[i], As + (wm * 32 + i * 16) * 40 + kk * 16, 40);
                #pragma unroll
                for (int j = 0; j < 2; j++)
                    wmma::load_matrix_sync(b[j], Bs + (kk * 16) * 136 + wn * 32 + j * 16, 136);
                #pragma unroll
                for (int i = 0; i < 2; i++)
                    #pragma unroll
                    for (int j = 0; j < 2; j++)
                        wmma::mma_sync(acc[i][j], a[i], b[j], acc[i][j]);
            }

            if (kt + 2 < KT) stage((kt + 2) % 3, (kt + 2) << 5);
        }

        // fused bias + layernorm epilogue (single 64-row phase)
        __syncthreads();
        #pragma unroll
        for (int i = 0; i < 2; i++)
            #pragma unroll
            for (int j = 0; j < 2; j++)
                wmma::store_matrix_sync(
                    smf + (size_t)(wm * 32 + i * 16) * 132 + wn * 32 + j * 16,
                    acc[i][j], 132, wmma::mem_row_major);
        __syncthreads();

        #pragma unroll
        for (int rr = 0; rr < 8; rr++) {
            int lr = warp * 8 + rr;
            int gm = row0 + lr;
            float4 v = *(const float4*)(smf + (size_t)lr * 132 + lane * 4);
            v.x += bnv.x; v.y += bnv.y; v.z += bnv.z; v.w += bnv.w;
            float s = v.x + v.y + v.z + v.w;
            #pragma unroll
            for (int o = 16; o; o >>= 1) s += __shfl_xor_sync(0xffffffffu, s, o);
            float mu = s * (1.f / 128.f);
            float dx = v.x - mu, dy = v.y - mu, dz = v.z - mu, dw = v.w - mu;
            float q = dx * dx + dy * dy + dz * dz + dw * dw;
            #pragma unroll
            for (int o = 16; o; o >>= 1) q += __shfl_xor_sync(0xffffffffu, q, o);
            float rstd = rsqrtf(q * (1.f / 128.f) + 1e-5f);
            float4 o4;
            o4.x = dx * rstd * ggv.x + bbv.x;
            o4.y = dy * rstd * ggv.y + bbv.y;
            o4.z = dz * rstd * ggv.z + bbv.z;
            o4.w = dw * rstd * ggv.w + bbv.w;
            if (gm < M) {
                if (doHalf) {
                    uint2 u = pack_h4(o4.x, o4.y, o4.z, o4.w);
                    *(uint2*)(CH + (size_t)gm * NN + lane * 4) = u;
                } else {
                    *(float4*)(C0 + (size_t)gm * NN + lane * 4) = o4;
                }
            }
        }
        __syncthreads();
    }
}

// ------- aggregation: smem edge staging, one exp per (edge,head) -------------------
// block = node (128 threads); fast path deg<=128, per-warp fallback otherwise
__global__ __launch_bounds__(128) void k_agg(const float* __restrict__ bgat) {
    __shared__ int   s_src[128];
    __shared__ float s_v[4][128];    // [head][edge] - conflict-free per-warp

    int n = blockIdx.x;
    int tid = threadIdx.x;
    int h = tid >> 5, lane = tid & 31;
    int beg = g_rowptr[n], end = g_rowptr[n + 1];
    int deg = end - beg;

    float4 acc = make_float4(0.f, 0.f, 0.f, 0.f);
    float iz;
    const __half* fbase = g_featH + h * Dd + lane * 4;

    if (deg <= 128) {
        if (tid < deg) {
            int s = g_csrsrc[beg + tid];
            s_src[tid] = s;
            float4 el = *(const float4*)(g_el + s * 4);
            float4 er = *(const float4*)(g_er + n * 4);
            float v0 = el.x + er.x; v0 = v0 > 0.f ? v0 : 0.2f * v0;
            float v1 = el.y + er.y; v1 = v1 > 0.f ? v1 : 0.2f * v1;
            float v2 = el.z + er.z; v2 = v2 > 0.f ? v2 : 0.2f * v2;
            float v3 = el.w + er.w; v3 = v3 > 0.f ? v3 : 0.2f * v3;
            s_v[0][tid] = v0; s_v[1][tid] = v1;
            s_v[2][tid] = v2; s_v[3][tid] = v3;
        }
        __syncthreads();

        float m = -1e30f;
        for (int e = lane; e < deg; e += 32) m = fmaxf(m, s_v[h][e]);
        #pragma unroll
        for (int o = 16; o; o >>= 1) m = fmaxf(m, __shfl_xor_sync(0xffffffffu, m, o));

        float z = 0.f;
        for (int e = lane; e < deg; e += 32) {
            float w = __expf(s_v[h][e] - m);
            s_v[h][e] = w;
            z += w;
        }
        #pragma unroll
        for (int o = 16; o; o >>= 1) z += __shfl_xor_sync(0xffffffffu, z, o);
        iz = 1.f / fmaxf(z, 1e-20f);
        __syncwarp();

        int e = 0;
        for (; e + 8 <= deg; e += 8) {
            int ss[8]; float ww[8]; uint2 uu[8];
            #pragma unroll
            for (int q = 0; q < 8; q++) { ss[q] = s_src[e + q]; ww[q] = s_v[h][e + q]; }
            #pragma unroll
            for (int q = 0; q < 8; q++) uu[q] = *(const uint2*)(fbase + (size_t)ss[q] * HDd);
            #pragma unroll
            for (int q = 0; q < 8; q++) {
                float2 a = __half22float2(*(__half2*)&uu[q].x);
                float2 b = __half22float2(*(__half2*)&uu[q].y);
                acc.x += ww[q] * a.x; acc.y += ww[q] * a.y;
                acc.z += ww[q] * b.x; acc.w += ww[q] * b.y;
            }
        }
        for (; e < deg; e++) {
            int s = s_src[e];
            float w = s_v[h][e];
            uint2 u = *(const uint2*)(fbase + (size_t)s * HDd);
            float2 a = __half22float2(*(__half2*)&u.x), b = __half22float2(*(__half2*)&u.y);
            acc.x += w * a.x; acc.y += w * a.y; acc.z += w * b.x; acc.w += w * b.y;
        }
    } else {
        float ern = g_er[n * 4 + h];
        float m = -1e30f, z = 0.f;
        for (int e = beg + lane; e < end; e += 32) {
            int s = g_csrsrc[e];
            float v = g_el[s * 4 + h] + ern;
            v = v > 0.f ? v : 0.2f * v;
            float M = fmaxf(m, v);
            z = z * __expf(m - M) + __expf(v - M);
            m = M;
        }
        #pragma unroll
        for (int o = 16; o; o >>= 1) {
            float mo = __shfl_xor_sync(0xffffffffu, m, o);
            float zo = __shfl_xor_sync(0xffffffffu, z, o);
            float M = fmaxf(m, mo);
            z = z * __expf(m - M) + zo * __expf(mo - M);
            m = M;
        }
        iz = 1.f / fmaxf(z, 1e-20f);
        for (int e = beg; e < end; e++) {
            int s = g_csrsrc[e];
            float v = g_el[s * 4 + h] + ern;
            v = v > 0.f ? v : 0.2f * v;
            float w = __expf(v - m);
            uint2 u = *(const uint2*)(fbase + (size_t)s * HDd);
            float2 a = __half22float2(*(__half2*)&u.x), b = __half22float2(*(__half2*)&u.y);
            acc.x += w * a.x; acc.y += w * a.y; acc.z += w * b.x; acc.w += w * b.y;
        }
    }

    size_t off = (size_t)n * HDd + h * Dd + lane * 4;
    uint2 ru = *(const uint2*)(g_resR + off);
    float2 ra = __half22float2(*(__half2*)&ru.x), rb = __half22float2(*(__half2*)&ru.y);
    float4 bg = *(const float4*)(bgat + h * Dd + lane * 4);
    float4 o;
    o.x = acc.x * iz + ra.x + bg.x;
    o.y = acc.y * iz + ra.y + bg.y;
    o.z = acc.z * iz + rb.x + bg.z;
    o.w = acc.w * iz + rb.y + bg.w;
    o.x = o.x > 0.f ? o.x : 0.01f * o.x;
    o.y = o.y > 0.f ? o.y : 0.01f * o.y;
    o.z = o.z > 0.f ? o.z : 0.01f * o.z;
    o.w = o.w > 0.f ? o.w : 0.01f * o.w;
    uint2 u = pack_h4(o.x, o.y, o.z, o.w);
    *(uint2*)(g_resH + off) = u;
}

// ---------------- launch ----------------
extern "C" void kernel_launch(void* const* d_in, const int* in_sizes, int n_in,
                              void* d_out, int out_size)
{
    const float* features = (const float*)d_in[0];
    const int*   src      = (const int*)  d_in[1];
    const int*   dst      = (const int*)  d_in[2];
    const float* W_fc     = (const float*)d_in[3];
    const float* attn_l   = (const float*)d_in[4];
    const float* attn_r   = (const float*)d_in[5];
    const float* W_res    = (const float*)d_in[6];
    const float* b_gat    = (const float*)d_in[7];
    const float* W_nrm    = (const float*)d_in[8];
    const float* b_nrm    = (const float*)d_in[9];
    const float* ln_g     = (const float*)d_in[10];
    const float* ln_b     = (const float*)d_in[11];
    float* out = (float*)d_out;

    __half *xh0, *xhA, *xhB, *wh, *resH;
    cudaGetSymbolAddress((void**)&xh0,  g_xh0);
    cudaGetSymbolAddress((void**)&xhA,  g_xhA);
    cudaGetSymbolAddress((void**)&xhB,  g_xhB);
    cudaGetSymbolAddress((void**)&wh,   g_wh);
    cudaGetSymbolAddress((void**)&resH, g_resH);

    static int smemSet = 0;
    if (!smemSet) {
        cudaFuncSetAttribute(gemm_h<Dd, HDd / 128>,
                             cudaFuncAttributeMaxDynamicSharedMemorySize, SMBYTES_H);
        smemSet = 1;
    }

    // preamble (fp16 convert + zero), count, scan -> dual GEMM is launch #4 for ncu
    k_pre<<<(NFEAT + 255) / 256, 256>>>(W_fc, W_res, W_nrm, features);
    k_count<<<(Ee + 255) / 256, 256>>>(dst);
    k_scan<<<1, 1024>>>();

    const __half* xin = xh0;
    for (int l = 0; l < Ll; l++) {
        const __half* Wf = wh + (size_t)l * WSZ;
        const __half* Wr = wh + (size_t)(Ll + l) * WSZ;
        const __half* Wn = wh + (size_t)(2 * Ll + l) * WSZ;

        // fused: featH(fp16) + el/er = xin@Wf ; resR(fp16) = xin@Wr  (persistent)
        gemm_h<Dd, HDd / 128><<<GRID_H, 256, SMBYTES_H>>>(
            xin, Wf, Wr, Nn, attn_l + l * Hh * Dd, attn_r + l * Hh * Dd);

        if (l == 0) k_fill<<<(Ee + 255) / 256, 256>>>(src, dst);

        k_agg<<<Nn, 128>>>(b_gat + l * HDd);

        // xout = layernorm(resH @ Wn + b_nrm), fused LN epilogue, persistent
        if (l == Ll - 1) {
            gemm_ln<HDd><<<GRID_LN, 256>>>(
                resH, Wn, out, nullptr, Nn,
                b_nrm + l * Dd, ln_g + l * Dd, ln_b + l * Dd, 0);
        } else {
            __half* xout = (l & 1) ? xhB : xhA;
            gemm_ln<HDd><<<GRID_LN, 256>>>(
                resH, Wn, nullptr, xout, Nn,
                b_nrm + l * Dd, ln_g + l * Dd, ln_b + l * Dd, 1);
            xin = xout;
        }
    }
}

// round 15
// speedup vs baseline: 1.1188x; 1.1188x over previous
#include <cuda_runtime.h>
#include <cuda_fp16.h>
#include <mma.h>
#include <cstdint>
using namespace nvcuda;

#define Nn 50000
#define Ee 800000
#define Hh 4
#define Dd 128
#define HDd 512
#define Ll 4

#define WSZ (Dd * HDd)          // 65536 per weight matrix
#define NWEIGHT (3 * Ll * WSZ)  // 786432
#define NFEAT (Nn * Dd)         // 6.4M

// gemm_h (dual) smem, BK=32, 3-stage (halves): 3 A bufs (128x40) + 3 B bufs (32x136)
#define ASTRIDE_H 5120          // 128*40
#define BBASE_H   15360         // 3*ASTRIDE_H
#define BSTRIDE_H 4352          // 32*136
// dynamic smem = max(ring 56832 B, epilogue 128x132 floats = 67584 B)
#define SMBYTES_H 67584

// gemm_ln smem, BK=32, 3-stage: 3 A bufs (64x40) + 3 B bufs (32x136) = 41472 B static
#define LN_ASTRIDE 2560         // 64*40
#define LN_BBASE   7680         // 3*LN_ASTRIDE
#define LN_SMBYTES ((LN_BBASE + 3 * BSTRIDE_H) * 2) // 41472

// ---------------- scratch (static device memory; no allocations) ----------------
__device__ __align__(16) __half g_featH[(size_t)Nn * HDd];  // fp16 feat (k_agg payload)
__device__ __align__(16) __half g_resR [(size_t)Nn * HDd];  // fp16 x@Wr (k_agg residual)
__device__ __align__(16) __half g_resH [(size_t)Nn * HDd];  // fp16 k_agg out (GEMM2 A)
__device__ __align__(16) float  g_el[Nn * Hh];
__device__ __align__(16) float  g_er[Nn * Hh];
__device__ __align__(16) __half g_xh0[(size_t)Nn * Dd];     // fp16 features
__device__ __align__(16) __half g_xhA[(size_t)Nn * Dd];
__device__ __align__(16) __half g_xhB[(size_t)Nn * Dd];
__device__ __align__(16) __half g_wh[NWEIGHT];              // fp16 weights
__device__ int g_deg[Nn];
__device__ int g_rowptr[Nn + 1];
__device__ int g_cursor[Nn];
__device__ int g_csrsrc[Ee];

// ---------------- preamble: convert weights+features to fp16, zero deg -------------
__global__ void k_pre(const float* __restrict__ Wf, const float* __restrict__ Wr,
                      const float* __restrict__ Wn, const float* __restrict__ feats)
{
    int i = blockIdx.x * blockDim.x + threadIdx.x;
    if (i < NFEAT) g_xh0[i] = __float2half_rn(feats[i]);
    if (i < Ll * WSZ) {
        g_wh[i]                = __float2half_rn(Wf[i]);
        g_wh[Ll * WSZ + i]     = __float2half_rn(Wr[i]);
        g_wh[2 * Ll * WSZ + i] = __float2half_rn(Wn[i]);
    }
    if (i < Nn) g_deg[i] = 0;
}

__global__ void k_count(const int* __restrict__ dst) {
    int i = blockIdx.x * blockDim.x + threadIdx.x;
    if (i < Ee) atomicAdd(&g_deg[dst[i]], 1);
}

// single-block warp-shuffle scan: 4 elems/thread, 4096/chunk, carry across chunks
__global__ void k_scan() {
    __shared__ int wsum[32];
    __shared__ int carry;
    int t = threadIdx.x, lane = t & 31, wid = t >> 5;
    if (t == 0) { carry = 0; g_rowptr[0] = 0; }
    __syncthreads();
    for (int base = 0; base < Nn; base += 4096) {
        int idx = base + t * 4;
        int v0 = (idx + 0 < Nn) ? g_deg[idx + 0] : 0;
        int v1 = (idx + 1 < Nn) ? g_deg[idx + 1] : 0;
        int v2 = (idx + 2 < Nn) ? g_deg[idx + 2] : 0;
        int v3 = (idx + 3 < Nn) ? g_deg[idx + 3] : 0;
        int s0 = v0, s1 = s0 + v1, s2 = s1 + v2, s3 = s2 + v3;
        int incl = s3;
        #pragma unroll
        for (int o = 1; o < 32; o <<= 1) {
            int x = __shfl_up_sync(0xffffffffu, incl, o);
            if (lane >= o) incl += x;
        }
        if (lane == 31) wsum[wid] = incl;
        __syncthreads();
        if (wid == 0) {
            int x = wsum[lane];
            #pragma unroll
            for (int o = 1; o < 32; o <<= 1) {
                int y = __shfl_up_sync(0xffffffffu, x, o);
                if (lane >= o) x += y;
            }
            wsum[lane] = x;
        }
        __syncthreads();
        int pre = carry + (wid ? wsum[wid - 1] : 0) + (incl - s3);
        if (idx + 0 < Nn) { g_rowptr[idx + 1] = pre + s0; g_cursor[idx + 0] = pre; }
        if (idx + 1 < Nn) { g_rowptr[idx + 2] = pre + s1; g_cursor[idx + 1] = pre + s0; }
        if (idx + 2 < Nn) { g_rowptr[idx + 3] = pre + s2; g_cursor[idx + 2] = pre + s1; }
        if (idx + 3 < Nn) { g_rowptr[idx + 4] = pre + s3; g_cursor[idx + 3] = pre + s2; }
        __syncthreads();
        if (t == 0) carry += wsum[31];
        __syncthreads();
    }
}

__global__ void k_fill(const int* __restrict__ src, const int* __restrict__ dst) {
    int i = blockIdx.x * blockDim.x + threadIdx.x;
    if (i < Ee) {
        int p = atomicAdd(&g_cursor[dst[i]], 1);
        g_csrsrc[p] = src[i];
    }
}

// ---------------- cp.async helper ----------------
__device__ __forceinline__ void cp16(uint32_t dst, const void* src, bool pred) {
    int sz = pred ? 16 : 0;
    asm volatile("cp.async.cg.shared.global [%0], [%1], 16, %2;\n"
                 :: "r"(dst), "l"(src), "r"(sz));
}

__device__ __forceinline__ uint2 pack_h4(float x, float y, float z, float w) {
    __half2 h0 = __floats2half2_rn(x, y);
    __half2 h1 = __floats2half2_rn(z, w);
    uint2 u;
    u.x = *reinterpret_cast<unsigned*>(&h0);
    u.y = *reinterpret_cast<unsigned*>(&h1);
    return u;
}

// ---------------- dual fp16 GEMM, CTA 128x128, BK=32, 3-stage ring ---------------
// Both halves epilogue via smem -> fp16 stores (guarded), single 128-row phase.
// feat half (bx<TPH): also computes attn el/er (head h == bx).
template<int K, int TPH>
__global__ __launch_bounds__(256) void gemm_h(
    const __half* __restrict__ A,
    const __half* __restrict__ B0, const __half* __restrict__ B1,
    int M, const float* __restrict__ p0, const float* __restrict__ p1)
{
    constexpr int NN = TPH * 128;
    extern __shared__ __half smh[];
    float* smf = reinterpret_cast<float*>(smh);

    const int tid = threadIdx.x;
    const int warp = tid >> 5;
    const int lane = tid & 31;
    const int wm = warp & 1, wn = warp >> 1;
    const int row0 = blockIdx.y * 128;

    int bx = blockIdx.x;
    bool isFeatHalf = (bx < TPH);
    const __half* B = B0;
    if (!isFeatHalf) { bx -= TPH; B = B1; }
    const int col0 = bx * 128;

    wmma::fragment<wmma::accumulator, 16, 16, 16, float> acc[4][2];
    #pragma unroll
    for (int i = 0; i < 4; i++)
        #pragma unroll
        for (int j = 0; j < 2; j++)
            wmma::fill_fragment(acc[i][j], 0.0f);

    constexpr int KT = K >> 5;   // BK=32

    auto stage = [&](int buf, int k0) {
        __half* As = smh + buf * ASTRIDE_H;
        __half* Bs = smh + BBASE_H + buf * BSTRIDE_H;
        #pragma unroll
        for (int p = 0; p < 2; p++) {   // A: 128 rows x 32 halves = 512 x 16B
            int c = tid + p * 256;
            int r = c >> 2, q = c & 3;
            int gm = row0 + r;
            const __half* srcp = A + (size_t)gm * K + k0 + q * 8;
            uint32_t d = (uint32_t)__cvta_generic_to_shared(&As[r * 40 + q * 8]);
            cp16(d, srcp, gm < M);
        }
        #pragma unroll
        for (int p = 0; p < 2; p++) {   // B: 32 rows x 128 halves = 512 x 16B
            int c = tid + p * 256;
            int r = c >> 4, q = c & 15;
            const __half* srcp = B + (size_t)(k0 + r) * NN + col0 + q * 8;
            uint32_t d = (uint32_t)__cvta_generic_to_shared(&Bs[r * 136 + q * 8]);
            cp16(d, srcp, true);
        }
        asm volatile("cp.async.commit_group;");
    };

    stage(0, 0);
    stage(1, 32);

    #pragma unroll
    for (int kt = 0; kt < KT; kt++) {
        if (kt + 2 < KT) asm volatile("cp.async.wait_group 1;");
        else             asm volatile("cp.async.wait_group 0;");
        __syncthreads();

        const int buf = kt % 3;
        const __half* As = smh + buf * ASTRIDE_H;
        const __half* Bs = smh + BBASE_H + buf * BSTRIDE_H;
        #pragma unroll
        for (int kk = 0; kk < 2; kk++) {
            wmma::fragment<wmma::matrix_a, 16, 16, 16, __half, wmma::row_major> a[4];
            wmma::fragment<wmma::matrix_b, 16, 16, 16, __half, wmma::row_major> b[2];
            #pragma unroll
            for (int i = 0; i < 4; i++)
                wmma::load_matrix_sync(a[i], As + (wm * 64 + i * 16) * 40 + kk * 16, 40);
            #pragma unroll
            for (int j = 0; j < 2; j++)
                wmma::load_matrix_sync(b[j], Bs + (kk * 16) * 136 + wn * 32 + j * 16, 136);
            #pragma unroll
            for (int i = 0; i < 4; i++)
                #pragma unroll
                for (int j = 0; j < 2; j++)
                    wmma::mma_sync(acc[i][j], a[i], b[j], acc[i][j]);
        }

        if (kt + 2 < KT) stage((kt + 2) % 3, (kt + 2) << 5);
    }

    // epilogue: acc -> smem (single 128-row phase) -> fp16 global (+ el/er feat half)
    float4 alv, arv;
    if (isFeatHalf) {
        alv = *(const float4*)(p0 + col0 + lane * 4);
        arv = *(const float4*)(p1 + col0 + lane * 4);
    }
    __half* outbase = isFeatHalf ? g_featH : g_resR;
    __syncthreads();
    #pragma unroll
    for (int i = 0; i < 4; i++)
        #pragma unroll
        for (int j = 0; j < 2; j++)
            wmma::store_matrix_sync(
                smf + (size_t)(wm * 64 + i * 16) * 132 + wn * 32 + j * 16,
                acc[i][j], 132, wmma::mem_row_major);
    __syncthreads();
    #pragma unroll
    for (int rr = 0; rr < 16; rr++) {
        int lr = warp * 16 + rr;
        int gm = row0 + lr;
        float4 v = *(const float4*)(smf + (size_t)lr * 132 + lane * 4);
        bool valid = gm < M;
        if (valid) {
            uint2 u = pack_h4(v.x, v.y, v.z, v.w);
            *(uint2*)(outbase + (size_t)gm * HDd + col0 + lane * 4) = u;
        }
        if (isFeatHalf) {
            float sl = v.x * alv.x + v.y * alv.y + v.z * alv.z + v.w * alv.w;
            float sr = v.x * arv.x + v.y * arv.y + v.z * arv.z + v.w * arv.w;
            #pragma unroll
            for (int o = 16; o; o >>= 1) {
                sl += __shfl_xor_sync(0xffffffffu, sl, o);
                sr += __shfl_xor_sync(0xffffffffu, sr, o);
            }
            if (lane == 0 && valid) {
                g_el[gm * Hh + bx] = sl;
                g_er[gm * Hh + bx] = sr;
            }
        }
    }
}

// ---------------- GEMM2 + LN: CTA 64x128, BK=32, 3-stage, warp 32x32 --------------
template<int K>
__global__ __launch_bounds__(256) void gemm_ln(
    const __half* __restrict__ A, const __half* __restrict__ B,
    float* __restrict__ C0, __half* __restrict__ CH, int M,
    const float* __restrict__ bn, const float* __restrict__ lng,
    const float* __restrict__ lnb, int doHalf)
{
    constexpr int NN = 128;
    __shared__ __align__(16) char smraw[LN_SMBYTES];
    __half* smh = reinterpret_cast<__half*>(smraw);
    float* smf = reinterpret_cast<float*>(smraw);

    const int tid = threadIdx.x;
    const int warp = tid >> 5;
    const int lane = tid & 31;
    const int wm = warp & 1, wn = warp >> 1;
    const int row0 = blockIdx.x * 64;

    wmma::fragment<wmma::accumulator, 16, 16, 16, float> acc[2][2];
    #pragma unroll
    for (int i = 0; i < 2; i++)
        #pragma unroll
        for (int j = 0; j < 2; j++)
            wmma::fill_fragment(acc[i][j], 0.0f);

    constexpr int KT = K >> 5;

    auto stage = [&](int buf, int k0) {
        __half* As = smh + buf * LN_ASTRIDE;
        __half* Bs = smh + LN_BBASE + buf * BSTRIDE_H;
        {   // A: 64 rows x 32 halves = 256 x 16B (1/thread)
            int r = tid >> 2, q = tid & 3;
            int gm = row0 + r;
            const __half* srcp = A + (size_t)gm * K + k0 + q * 8;
            uint32_t d = (uint32_t)__cvta_generic_to_shared(&As[r * 40 + q * 8]);
            cp16(d, srcp, gm < M);
        }
        #pragma unroll
        for (int p = 0; p < 2; p++) {   // B: 32 rows x 128 halves = 512 x 16B
            int c = tid + p * 256;
            int r = c >> 4, q = c & 15;
            const __half* srcp = B + (size_t)(k0 + r) * NN + q * 8;
            uint32_t d = (uint32_t)__cvta_generic_to_shared(&Bs[r * 136 + q * 8]);
            cp16(d, srcp, true);
        }
        asm volatile("cp.async.commit_group;");
    };

    stage(0, 0);
    stage(1, 32);

    #pragma unroll
    for (int kt = 0; kt < KT; kt++) {
        if (kt + 2 < KT) asm volatile("cp.async.wait_group 1;");
        else             asm volatile("cp.async.wait_group 0;");
        __syncthreads();

        const int buf = kt % 3;
        const __half* As = smh + buf * LN_ASTRIDE;
        const __half* Bs = smh + LN_BBASE + buf * BSTRIDE_H;
        #pragma unroll
        for (int kk = 0; kk < 2; kk++) {
            wmma::fragment<wmma::matrix_a, 16, 16, 16, __half, wmma::row_major> a[2];
            wmma::fragment<wmma::matrix_b, 16, 16, 16, __half, wmma::row_major> b[2];
            #pragma unroll
            for (int i = 0; i < 2; i++)
                wmma::load_matrix_sync(a[i], As + (wm * 32 + i * 16) * 40 + kk * 16, 40);
            #pragma unroll
            for (int j = 0; j < 2; j++)
                wmma::load_matrix_sync(b[j], Bs + (kk * 16) * 136 + wn * 32 + j * 16, 136);
            #pragma unroll
            for (int i = 0; i < 2; i++)
                #pragma unroll
                for (int j = 0; j < 2; j++)
                    wmma::mma_sync(acc[i][j], a[i], b[j], acc[i][j]);
        }

        if (kt + 2 < KT) stage((kt + 2) % 3, (kt + 2) << 5);
    }

    // fused bias + layernorm epilogue (single 64-row phase)
    __syncthreads();
    #pragma unroll
    for (int i = 0; i < 2; i++)
        #pragma unroll
        for (int j = 0; j < 2; j++)
            wmma::store_matrix_sync(
                smf + (size_t)(wm * 32 + i * 16) * 132 + wn * 32 + j * 16,
                acc[i][j], 132, wmma::mem_row_major);
    __syncthreads();

    float4 bnv = ((const float4*)bn)[lane];
    float4 ggv = ((const float4*)lng)[lane];
    float4 bbv = ((const float4*)lnb)[lane];
    #pragma unroll
    for (int rr = 0; rr < 8; rr++) {
        int lr = warp * 8 + rr;
        int gm = row0 + lr;
        float4 v = *(const float4*)(smf + (size_t)lr * 132 + lane * 4);
        v.x += bnv.x; v.y += bnv.y; v.z += bnv.z; v.w += bnv.w;
        float s = v.x + v.y + v.z + v.w;
        #pragma unroll
        for (int o = 16; o; o >>= 1) s += __shfl_xor_sync(0xffffffffu, s, o);
        float mu = s * (1.f / 128.f);
        float dx = v.x - mu, dy = v.y - mu, dz = v.z - mu, dw = v.w - mu;
        float q = dx * dx + dy * dy + dz * dz + dw * dw;
        #pragma unroll
        for (int o = 16; o; o >>= 1) q += __shfl_xor_sync(0xffffffffu, q, o);
        float rstd = rsqrtf(q * (1.f / 128.f) + 1e-5f);
        float4 o4;
        o4.x = dx * rstd * ggv.x + bbv.x;
        o4.y = dy * rstd * ggv.y + bbv.y;
        o4.z = dz * rstd * ggv.z + bbv.z;
        o4.w = dw * rstd * ggv.w + bbv.w;
        if (gm < M) {
            if (doHalf) {
                uint2 u = pack_h4(o4.x, o4.y, o4.z, o4.w);
                *(uint2*)(CH + (size_t)gm * NN + lane * 4) = u;
            } else {
                *(float4*)(C0 + (size_t)gm * NN + lane * 4) = o4;
            }
        }
    }
}

// ------- aggregation: smem edge staging, one exp per (edge,head) -------------------
// block = node (128 threads); fast path deg<=128, per-warp fallback otherwise
__global__ __launch_bounds__(128) void k_agg(const float* __restrict__ bgat) {
    __shared__ int   s_src[128];
    __shared__ float s_v[4][128];    // [head][edge] - conflict-free per-warp

    int n = blockIdx.x;
    int tid = threadIdx.x;
    int h = tid >> 5, lane = tid & 31;
    int beg = g_rowptr[n], end = g_rowptr[n + 1];
    int deg = end - beg;

    float4 acc = make_float4(0.f, 0.f, 0.f, 0.f);
    float iz;
    const __half* fbase = g_featH + h * Dd + lane * 4;

    if (deg <= 128) {
        if (tid < deg) {
            int s = g_csrsrc[beg + tid];
            s_src[tid] = s;
            float4 el = *(const float4*)(g_el + s * 4);
            float4 er = *(const float4*)(g_er + n * 4);
            float v0 = el.x + er.x; v0 = v0 > 0.f ? v0 : 0.2f * v0;
            float v1 = el.y + er.y; v1 = v1 > 0.f ? v1 : 0.2f * v1;
            float v2 = el.z + er.z; v2 = v2 > 0.f ? v2 : 0.2f * v2;
            float v3 = el.w + er.w; v3 = v3 > 0.f ? v3 : 0.2f * v3;
            s_v[0][tid] = v0; s_v[1][tid] = v1;
            s_v[2][tid] = v2; s_v[3][tid] = v3;
        }
        __syncthreads();

        float m = -1e30f;
        for (int e = lane; e < deg; e += 32) m = fmaxf(m, s_v[h][e]);
        #pragma unroll
        for (int o = 16; o; o >>= 1) m = fmaxf(m, __shfl_xor_sync(0xffffffffu, m, o));

        float z = 0.f;
        for (int e = lane; e < deg; e += 32) {
            float w = __expf(s_v[h][e] - m);
            s_v[h][e] = w;
            z += w;
        }
        #pragma unroll
        for (int o = 16; o; o >>= 1) z += __shfl_xor_sync(0xffffffffu, z, o);
        iz = 1.f / fmaxf(z, 1e-20f);
        __syncwarp();

        int e = 0;
        for (; e + 8 <= deg; e += 8) {
            int ss[8]; float ww[8]; uint2 uu[8];
            #pragma unroll
            for (int q = 0; q < 8; q++) { ss[q] = s_src[e + q]; ww[q] = s_v[h][e + q]; }
            #pragma unroll
            for (int q = 0; q < 8; q++) uu[q] = *(const uint2*)(fbase + (size_t)ss[q] * HDd);
            #pragma unroll
            for (int q = 0; q < 8; q++) {
                float2 a = __half22float2(*(__half2*)&uu[q].x);
                float2 b = __half22float2(*(__half2*)&uu[q].y);
                acc.x += ww[q] * a.x; acc.y += ww[q] * a.y;
                acc.z += ww[q] * b.x; acc.w += ww[q] * b.y;
            }
        }
        for (; e < deg; e++) {
            int s = s_src[e];
            float w = s_v[h][e];
            uint2 u = *(const uint2*)(fbase + (size_t)s * HDd);
            float2 a = __half22float2(*(__half2*)&u.x), b = __half22float2(*(__half2*)&u.y);
            acc.x += w * a.x; acc.y += w * a.y; acc.z += w * b.x; acc.w += w * b.y;
        }
    } else {
        float ern = g_er[n * 4 + h];
        float m = -1e30f, z = 0.f;
        for (int e = beg + lane; e < end; e += 32) {
            int s = g_csrsrc[e];
            float v = g_el[s * 4 + h] + ern;
            v = v > 0.f ? v : 0.2f * v;
            float M = fmaxf(m, v);
            z = z * __expf(m - M) + __expf(v - M);
            m = M;
        }
        #pragma unroll
        for (int o = 16; o; o >>= 1) {
            float mo = __shfl_xor_sync(0xffffffffu, m, o);
            float zo = __shfl_xor_sync(0xffffffffu, z, o);
            float M = fmaxf(m, mo);
            z = z * __expf(m - M) + zo * __expf(mo - M);
            m = M;
        }
        iz = 1.f / fmaxf(z, 1e-20f);
        for (int e = beg; e < end; e++) {
            int s = g_csrsrc[e];
            float v = g_el[s * 4 + h] + ern;
            v = v > 0.f ? v : 0.2f * v;
            float w = __expf(v - m);
            uint2 u = *(const uint2*)(fbase + (size_t)s * HDd);
            float2 a = __half22float2(*(__half2*)&u.x), b = __half22float2(*(__half2*)&u.y);
            acc.x += w * a.x; acc.y += w * a.y; acc.z += w * b.x; acc.w += w * b.y;
        }
    }

    size_t off = (size_t)n * HDd + h * Dd + lane * 4;
    uint2 ru = *(const uint2*)(g_resR + off);
    float2 ra = __half22float2(*(__half2*)&ru.x), rb = __half22float2(*(__half2*)&ru.y);
    float4 bg = *(const float4*)(bgat + h * Dd + lane * 4);
    float4 o;
    o.x = acc.x * iz + ra.x + bg.x;
    o.y = acc.y * iz + ra.y + bg.y;
    o.z = acc.z * iz + rb.x + bg.z;
    o.w = acc.w * iz + rb.y + bg.w;
    o.x = o.x > 0.f ? o.x : 0.01f * o.x;
    o.y = o.y > 0.f ? o.y : 0.01f * o.y;
    o.z = o.z > 0.f ? o.z : 0.01f * o.z;
    o.w = o.w > 0.f ? o.w : 0.01f * o.w;
    uint2 u = pack_h4(o.x, o.y, o.z, o.w);
    *(uint2*)(g_resH + off) = u;
}

// ---------------- launch ----------------
extern "C" void kernel_launch(void* const* d_in, const int* in_sizes, int n_in,
                              void* d_out, int out_size)
{
    const float* features = (const float*)d_in[0];
    const int*   src      = (const int*)  d_in[1];
    const int*   dst      = (const int*)  d_in[2];
    const float* W_fc     = (const float*)d_in[3];
    const float* attn_l   = (const float*)d_in[4];
    const float* attn_r   = (const float*)d_in[5];
    const float* W_res    = (const float*)d_in[6];
    const float* b_gat    = (const float*)d_in[7];
    const float* W_nrm    = (const float*)d_in[8];
    const float* b_nrm    = (const float*)d_in[9];
    const float* ln_g     = (const float*)d_in[10];
    const float* ln_b     = (const float*)d_in[11];
    float* out = (float*)d_out;

    __half *xh0, *xhA, *xhB, *wh, *resH;
    cudaGetSymbolAddress((void**)&xh0,  g_xh0);
    cudaGetSymbolAddress((void**)&xhA,  g_xhA);
    cudaGetSymbolAddress((void**)&xhB,  g_xhB);
    cudaGetSymbolAddress((void**)&wh,   g_wh);
    cudaGetSymbolAddress((void**)&resH, g_resH);

    static int smemSet = 0;
    if (!smemSet) {
        cudaFuncSetAttribute(gemm_h<Dd, HDd / 128>,
                             cudaFuncAttributeMaxDynamicSharedMemorySize, SMBYTES_H);
        smemSet = 1;
    }

    // preamble (fp16 convert + zero), count, scan -> dual GEMM is launch #4 for ncu
    k_pre<<<(NFEAT + 255) / 256, 256>>>(W_fc, W_res, W_nrm, features);
    k_count<<<(Ee + 255) / 256, 256>>>(dst);
    k_scan<<<1, 1024>>>();

    const int gy = (Nn + 127) / 128;   // 391
    const int gln = (Nn + 63) / 64;    // 782

    const __half* xin = xh0;
    for (int l = 0; l < Ll; l++) {
        const __half* Wf = wh + (size_t)l * WSZ;
        const __half* Wr = wh + (size_t)(Ll + l) * WSZ;
        const __half* Wn = wh + (size_t)(2 * Ll + l) * WSZ;

        // fused: featH(fp16) + el/er = xin@Wf ; resR(fp16) = xin@Wr
        dim3 g1(2 * (HDd / 128), gy);
        gemm_h<Dd, HDd / 128><<<g1, 256, SMBYTES_H>>>(
            xin, Wf, Wr, Nn, attn_l + l * Hh * Dd, attn_r + l * Hh * Dd);

        if (l == 0) k_fill<<<(Ee + 255) / 256, 256>>>(src, dst);

        k_agg<<<Nn, 128>>>(b_gat + l * HDd);

        // xout = layernorm(resH @ Wn + b_nrm), fused LN epilogue, 64-row tiles
        if (l == Ll - 1) {
            gemm_ln<HDd><<<gln, 256>>>(
                resH, Wn, out, nullptr, Nn,
                b_nrm + l * Dd, ln_g + l * Dd, ln_b + l * Dd, 0);
        } else {
            __half* xout = (l & 1) ? xhB : xhA;
            gemm_ln<HDd><<<gln, 256>>>(
                resH, Wn, nullptr, xout, Nn,
                b_nrm + l * Dd, ln_g + l * Dd, ln_b + l * Dd, 1);
            xin = xout;
        }
    }
}

// round 17
// speedup vs baseline: 1.1432x; 1.0219x over previous
#include <cuda_runtime.h>
#include <cuda_fp16.h>
#include <mma.h>
#include <cstdint>
using namespace nvcuda;

#define Nn 50000
#define Ee 800000
#define Hh 4
#define Dd 128
#define HDd 512
#define Ll 4

#define WSZ (Dd * HDd)          // 65536 per weight matrix
#define NWEIGHT (3 * Ll * WSZ)  // 786432
#define NFEAT (Nn * Dd)         // 6.4M

// gemm_h (dual) smem, BK=32, 3-stage (halves): 3 A bufs (128x40) + 3 B bufs (32x136)
#define ASTRIDE_H 5120          // 128*40
#define BBASE_H   15360         // 3*ASTRIDE_H
#define BSTRIDE_H 4352          // 32*136
#define SMBYTES_H ((BBASE_H + 3 * BSTRIDE_H) * 2)   // 56832 B (dynamic)

// gemm_ln smem, BK=32, 3-stage: 3 A bufs (64x40) + 3 B bufs (32x136) = 41472 B static
#define LN_ASTRIDE 2560         // 64*40
#define LN_BBASE   7680         // 3*LN_ASTRIDE
#define LN_SMBYTES ((LN_BBASE + 3 * BSTRIDE_H) * 2) // 41472

// ---------------- scratch (static device memory; no allocations) ----------------
__device__ __align__(16) __half g_featH[(size_t)Nn * HDd];  // fp16 feat (k_agg payload)
__device__ __align__(16) __half g_resR [(size_t)Nn * HDd];  // fp16 x@Wr (k_agg residual)
__device__ __align__(16) __half g_resH [(size_t)Nn * HDd];  // fp16 k_agg out (GEMM2 A)
__device__ __align__(16) float  g_el[Nn * Hh];
__device__ __align__(16) float  g_er[Nn * Hh];
__device__ __align__(16) __half g_xh0[(size_t)Nn * Dd];     // fp16 features
__device__ __align__(16) __half g_xhA[(size_t)Nn * Dd];
__device__ __align__(16) __half g_xhB[(size_t)Nn * Dd];
__device__ __align__(16) __half g_wh[NWEIGHT];              // fp16 weights
__device__ int g_deg[Nn];
__device__ int g_rowptr[Nn + 1];
__device__ int g_cursor[Nn];
__device__ int g_csrsrc[Ee];

// ---------------- helpers ----------------
__device__ __forceinline__ void cp16(uint32_t dst, const void* src, bool pred) {
    int sz = pred ? 16 : 0;
    asm volatile("cp.async.cg.shared.global [%0], [%1], 16, %2;\n"
                 :: "r"(dst), "l"(src), "r"(sz));
}

__device__ __forceinline__ uint2 pack_h4(float x, float y, float z, float w) {
    __half2 h0 = __floats2half2_rn(x, y);
    __half2 h1 = __floats2half2_rn(z, w);
    uint2 u;
    u.x = *reinterpret_cast<unsigned*>(&h0);
    u.y = *reinterpret_cast<unsigned*>(&h1);
    return u;
}

// ---------------- preamble: fp16 convert (vectorized), zero deg -------------------
// 4 floats/thread: grid covers NFEAT/4 = 1.6M chunks
__global__ void k_pre(const float* __restrict__ Wf, const float* __restrict__ Wr,
                      const float* __restrict__ Wn, const float* __restrict__ feats)
{
    int i = blockIdx.x * blockDim.x + threadIdx.x;
    if (i < NFEAT / 4) {
        float4 v = ((const float4*)feats)[i];
        ((uint2*)g_xh0)[i] = pack_h4(v.x, v.y, v.z, v.w);
    }
    if (i < Ll * WSZ / 4) {
        float4 a = ((const float4*)Wf)[i];
        float4 b = ((const float4*)Wr)[i];
        float4 c = ((const float4*)Wn)[i];
        ((uint2*)g_wh)[i]                    = pack_h4(a.x, a.y, a.z, a.w);
        ((uint2*)g_wh)[Ll * WSZ / 4 + i]     = pack_h4(b.x, b.y, b.z, b.w);
        ((uint2*)g_wh)[2 * Ll * WSZ / 4 + i] = pack_h4(c.x, c.y, c.z, c.w);
    }
    if (i < Nn) g_deg[i] = 0;
}

__global__ void k_count(const int* __restrict__ dst) {
    int i = blockIdx.x * blockDim.x + threadIdx.x;
    if (i < Ee) atomicAdd(&g_deg[dst[i]], 1);
}

// single-block warp-shuffle scan: 4 elems/thread, 4096/chunk, carry across chunks
__global__ void k_scan() {
    __shared__ int wsum[32];
    __shared__ int carry;
    int t = threadIdx.x, lane = t & 31, wid = t >> 5;
    if (t == 0) { carry = 0; g_rowptr[0] = 0; }
    __syncthreads();
    for (int base = 0; base < Nn; base += 4096) {
        int idx = base + t * 4;
        int v0 = (idx + 0 < Nn) ? g_deg[idx + 0] : 0;
        int v1 = (idx + 1 < Nn) ? g_deg[idx + 1] : 0;
        int v2 = (idx + 2 < Nn) ? g_deg[idx + 2] : 0;
        int v3 = (idx + 3 < Nn) ? g_deg[idx + 3] : 0;
        int s0 = v0, s1 = s0 + v1, s2 = s1 + v2, s3 = s2 + v3;
        int incl = s3;
        #pragma unroll
        for (int o = 1; o < 32; o <<= 1) {
            int x = __shfl_up_sync(0xffffffffu, incl, o);
            if (lane >= o) incl += x;
        }
        if (lane == 31) wsum[wid] = incl;
        __syncthreads();
        if (wid == 0) {
            int x = wsum[lane];
            #pragma unroll
            for (int o = 1; o < 32; o <<= 1) {
                int y = __shfl_up_sync(0xffffffffu, x, o);
                if (lane >= o) x += y;
            }
            wsum[lane] = x;
        }
        __syncthreads();
        int pre = carry + (wid ? wsum[wid - 1] : 0) + (incl - s3);
        if (idx + 0 < Nn) { g_rowptr[idx + 1] = pre + s0; g_cursor[idx + 0] = pre; }
        if (idx + 1 < Nn) { g_rowptr[idx + 2] = pre + s1; g_cursor[idx + 1] = pre + s0; }
        if (idx + 2 < Nn) { g_rowptr[idx + 3] = pre + s2; g_cursor[idx + 2] = pre + s1; }
        if (idx + 3 < Nn) { g_rowptr[idx + 4] = pre + s3; g_cursor[idx + 3] = pre + s2; }
        __syncthreads();
        if (t == 0) carry += wsum[31];
        __syncthreads();
    }
}

__global__ void k_fill(const int* __restrict__ src, const int* __restrict__ dst) {
    int i = blockIdx.x * blockDim.x + threadIdx.x;
    if (i < Ee) {
        int p = atomicAdd(&g_cursor[dst[i]], 1);
        g_csrsrc[p] = src[i];
    }
}

// ---------------- dual fp16 GEMM, CTA 128x128, BK=32, 3-stage ring ---------------
// Both halves epilogue via smem -> fp16 stores (guarded), two 64-row phases.
// feat half (bx<TPH): also computes attn el/er (head h == bx).
template<int K, int TPH>
__global__ __launch_bounds__(256) void gemm_h(
    const __half* __restrict__ A,
    const __half* __restrict__ B0, const __half* __restrict__ B1,
    int M, const float* __restrict__ p0, const float* __restrict__ p1)
{
    constexpr int NN = TPH * 128;
    extern __shared__ __half smh[];
    float* smf = reinterpret_cast<float*>(smh);

    const int tid = threadIdx.x;
    const int warp = tid >> 5;
    const int lane = tid & 31;
    const int wm = warp & 1, wn = warp >> 1;
    const int row0 = blockIdx.y * 128;

    int bx = blockIdx.x;
    bool isFeatHalf = (bx < TPH);
    const __half* B = B0;
    if (!isFeatHalf) { bx -= TPH; B = B1; }
    const int col0 = bx * 128;

    wmma::fragment<wmma::accumulator, 16, 16, 16, float> acc[4][2];
    #pragma unroll
    for (int i = 0; i < 4; i++)
        #pragma unroll
        for (int j = 0; j < 2; j++)
            wmma::fill_fragment(acc[i][j], 0.0f);

    constexpr int KT = K >> 5;   // BK=32

    auto stage = [&](int buf, int k0) {
        __half* As = smh + buf * ASTRIDE_H;
        __half* Bs = smh + BBASE_H + buf * BSTRIDE_H;
        #pragma unroll
        for (int p = 0; p < 2; p++) {   // A: 128 rows x 32 halves = 512 x 16B
            int c = tid + p * 256;
            int r = c >> 2, q = c & 3;
            int gm = row0 + r;
            const __half* srcp = A + (size_t)gm * K + k0 + q * 8;
            uint32_t d = (uint32_t)__cvta_generic_to_shared(&As[r * 40 + q * 8]);
            cp16(d, srcp, gm < M);
        }
        #pragma unroll
        for (int p = 0; p < 2; p++) {   // B: 32 rows x 128 halves = 512 x 16B
            int c = tid + p * 256;
            int r = c >> 4, q = c & 15;
            const __half* srcp = B + (size_t)(k0 + r) * NN + col0 + q * 8;
            uint32_t d = (uint32_t)__cvta_generic_to_shared(&Bs[r * 136 + q * 8]);
            cp16(d, srcp, true);
        }
        asm volatile("cp.async.commit_group;");
    };

    stage(0, 0);
    stage(1, 32);

    #pragma unroll
    for (int kt = 0; kt < KT; kt++) {
        if (kt + 2 < KT) asm volatile("cp.async.wait_group 1;");
        else             asm volatile("cp.async.wait_group 0;");
        __syncthreads();

        const int buf = kt % 3;
        const __half* As = smh + buf * ASTRIDE_H;
        const __half* Bs = smh + BBASE_H + buf * BSTRIDE_H;
        #pragma unroll
        for (int kk = 0; kk < 2; kk++) {
            wmma::fragment<wmma::matrix_a, 16, 16, 16, __half, wmma::row_major> a[4];
            wmma::fragment<wmma::matrix_b, 16, 16, 16, __half, wmma::row_major> b[2];
            #pragma unroll
            for (int i = 0; i < 4; i++)
                wmma::load_matrix_sync(a[i], As + (wm * 64 + i * 16) * 40 + kk * 16, 40);
            #pragma unroll
            for (int j = 0; j < 2; j++)
                wmma::load_matrix_sync(b[j], Bs + (kk * 16) * 136 + wn * 32 + j * 16, 136);
            #pragma unroll
            for (int i = 0; i < 4; i++)
                #pragma unroll
                for (int j = 0; j < 2; j++)
                    wmma::mma_sync(acc[i][j], a[i], b[j], acc[i][j]);
        }

        if (kt + 2 < KT) stage((kt + 2) % 3, (kt + 2) << 5);
    }

    // epilogue: acc -> smem (two 64-row phases) -> fp16 global (+ el/er feat half)
    float* sC = smf;   // 64 x 132 floats
    float4 alv, arv;
    if (isFeatHalf) {
        alv = *(const float4*)(p0 + col0 + lane * 4);
        arv = *(const float4*)(p1 + col0 + lane * 4);
    }
    __half* outbase = isFeatHalf ? g_featH : g_resR;
    __syncthreads();
    #pragma unroll
    for (int p = 0; p < 2; p++) {
        if (wm == p) {
            #pragma unroll
            for (int i = 0; i < 4; i++)
                #pragma unroll
                for (int j = 0; j < 2; j++)
                    wmma::store_matrix_sync(
                        sC + (size_t)(i * 16) * 132 + wn * 32 + j * 16,
                        acc[i][j], 132, wmma::mem_row_major);
        }
        __syncthreads();
        #pragma unroll
        for (int rr = 0; rr < 8; rr++) {
            int lr = warp * 8 + rr;
            int gm = row0 + p * 64 + lr;
            float4 v = *(const float4*)(sC + (size_t)lr * 132 + lane * 4);
            bool valid = gm < M;
            if (valid) {
                uint2 u = pack_h4(v.x, v.y, v.z, v.w);
                *(uint2*)(outbase + (size_t)gm * HDd + col0 + lane * 4) = u;
            }
            if (isFeatHalf) {
                float sl = v.x * alv.x + v.y * alv.y + v.z * alv.z + v.w * alv.w;
                float sr = v.x * arv.x + v.y * arv.y + v.z * arv.z + v.w * arv.w;
                #pragma unroll
                for (int o = 16; o; o >>= 1) {
                    sl += __shfl_xor_sync(0xffffffffu, sl, o);
                    sr += __shfl_xor_sync(0xffffffffu, sr, o);
                }
                if (lane == 0 && valid) {
                    g_el[gm * Hh + bx] = sl;
                    g_er[gm * Hh + bx] = sr;
                }
            }
        }
        __syncthreads();
    }
}

// ---------------- GEMM2 + LN: CTA 64x128, BK=32, 3-stage, warp 32x32 --------------
template<int K>
__global__ __launch_bounds__(256) void gemm_ln(
    const __half* __restrict__ A, const __half* __restrict__ B,
    float* __restrict__ C0, __half* __restrict__ CH, int M,
    const float* __restrict__ bn, const float* __restrict__ lng,
    const float* __restrict__ lnb, int doHalf)
{
    constexpr int NN = 128;
    __shared__ __align__(16) char smraw[LN_SMBYTES];
    __half* smh = reinterpret_cast<__half*>(smraw);
    float* smf = reinterpret_cast<float*>(smraw);

    const int tid = threadIdx.x;
    const int warp = tid >> 5;
    const int lane = tid & 31;
    const int wm = warp & 1, wn = warp >> 1;
    const int row0 = blockIdx.x * 64;

    wmma::fragment<wmma::accumulator, 16, 16, 16, float> acc[2][2];
    #pragma unroll
    for (int i = 0; i < 2; i++)
        #pragma unroll
        for (int j = 0; j < 2; j++)
            wmma::fill_fragment(acc[i][j], 0.0f);

    constexpr int KT = K >> 5;

    auto stage = [&](int buf, int k0) {
        __half* As = smh + buf * LN_ASTRIDE;
        __half* Bs = smh + LN_BBASE + buf * BSTRIDE_H;
        {   // A: 64 rows x 32 halves = 256 x 16B (1/thread)
            int r = tid >> 2, q = tid & 3;
            int gm = row0 + r;
            const __half* srcp = A + (size_t)gm * K + k0 + q * 8;
            uint32_t d = (uint32_t)__cvta_generic_to_shared(&As[r * 40 + q * 8]);
            cp16(d, srcp, gm < M);
        }
        #pragma unroll
        for (int p = 0; p < 2; p++) {   // B: 32 rows x 128 halves = 512 x 16B
            int c = tid + p * 256;
            int r = c >> 4, q = c & 15;
            const __half* srcp = B + (size_t)(k0 + r) * NN + q * 8;
            uint32_t d = (uint32_t)__cvta_generic_to_shared(&Bs[r * 136 + q * 8]);
            cp16(d, srcp, true);
        }
        asm volatile("cp.async.commit_group;");
    };

    stage(0, 0);
    stage(1, 32);

    #pragma unroll
    for (int kt = 0; kt < KT; kt++) {
        if (kt + 2 < KT) asm volatile("cp.async.wait_group 1;");
        else             asm volatile("cp.async.wait_group 0;");
        __syncthreads();

        const int buf = kt % 3;
        const __half* As = smh + buf * LN_ASTRIDE;
        const __half* Bs = smh + LN_BBASE + buf * BSTRIDE_H;
        #pragma unroll
        for (int kk = 0; kk < 2; kk++) {
            wmma::fragment<wmma::matrix_a, 16, 16, 16, __half, wmma::row_major> a[2];
            wmma::fragment<wmma::matrix_b, 16, 16, 16, __half, wmma::row_major> b[2];
            #pragma unroll
            for (int i = 0; i < 2; i++)
                wmma::load_matrix_sync(a[i], As + (wm * 32 + i * 16) * 40 + kk * 16, 40);
            #pragma unroll
            for (int j = 0; j < 2; j++)
                wmma::load_matrix_sync(b[j], Bs + (kk * 16) * 136 + wn * 32 + j * 16, 136);
            #pragma unroll
            for (int i = 0; i < 2; i++)
                #pragma unroll
                for (int j = 0; j < 2; j++)
                    wmma::mma_sync(acc[i][j], a[i], b[j], acc[i][j]);
        }

        if (kt + 2 < KT) stage((kt + 2) % 3, (kt + 2) << 5);
    }

    // fused bias + layernorm epilogue (single 64-row phase)
    __syncthreads();
    #pragma unroll
    for (int i = 0; i < 2; i++)
        #pragma unroll
        for (int j = 0; j < 2; j++)
            wmma::store_matrix_sync(
                smf + (size_t)(wm * 32 + i * 16) * 132 + wn * 32 + j * 16,
                acc[i][j], 132, wmma::mem_row_major);
    __syncthreads();

    float4 bnv = ((const float4*)bn)[lane];
    float4 ggv = ((const float4*)lng)[lane];
    float4 bbv = ((const float4*)lnb)[lane];
    #pragma unroll
    for (int rr = 0; rr < 8; rr++) {
        int lr = warp * 8 + rr;
        int gm = row0 + lr;
        float4 v = *(const float4*)(smf + (size_t)lr * 132 + lane * 4);
        v.x += bnv.x; v.y += bnv.y; v.z += bnv.z; v.w += bnv.w;
        float s = v.x + v.y + v.z + v.w;
        #pragma unroll
        for (int o = 16; o; o >>= 1) s += __shfl_xor_sync(0xffffffffu, s, o);
        float mu = s * (1.f / 128.f);
        float dx = v.x - mu, dy = v.y - mu, dz = v.z - mu, dw = v.w - mu;
        float q = dx * dx + dy * dy + dz * dz + dw * dw;
        #pragma unroll
        for (int o = 16; o; o >>= 1) q += __shfl_xor_sync(0xffffffffu, q, o);
        float rstd = rsqrtf(q * (1.f / 128.f) + 1e-5f);
        float4 o4;
        o4.x = dx * rstd * ggv.x + bbv.x;
        o4.y = dy * rstd * ggv.y + bbv.y;
        o4.z = dz * rstd * ggv.z + bbv.z;
        o4.w = dw * rstd * ggv.w + bbv.w;
        if (gm < M) {
            if (doHalf) {
                uint2 u = pack_h4(o4.x, o4.y, o4.z, o4.w);
                *(uint2*)(CH + (size_t)gm * NN + lane * 4) = u;
            } else {
                *(float4*)(C0 + (size_t)gm * NN + lane * 4) = o4;
            }
        }
    }
}

// ------- aggregation: smem edge staging, one exp per (edge,head) -------------------
// block = node (128 threads); fast path deg<=128, per-warp fallback otherwise
__global__ __launch_bounds__(128) void k_agg(const float* __restrict__ bgat) {
    __shared__ int   s_src[128];
    __shared__ float s_v[4][128];    // [head][edge] - conflict-free per-warp

    int n = blockIdx.x;
    int tid = threadIdx.x;
    int h = tid >> 5, lane = tid & 31;
    int beg = g_rowptr[n], end = g_rowptr[n + 1];
    int deg = end - beg;

    float4 acc = make_float4(0.f, 0.f, 0.f, 0.f);
    float iz;
    const __half* fbase = g_featH + h * Dd + lane * 4;

    if (deg <= 128) {
        if (tid < deg) {
            int s = g_csrsrc[beg + tid];
            s_src[tid] = s;
            float4 el = *(const float4*)(g_el + s * 4);
            float4 er = *(const float4*)(g_er + n * 4);
            float v0 = el.x + er.x; v0 = v0 > 0.f ? v0 : 0.2f * v0;
            float v1 = el.y + er.y; v1 = v1 > 0.f ? v1 : 0.2f * v1;
            float v2 = el.z + er.z; v2 = v2 > 0.f ? v2 : 0.2f * v2;
            float v3 = el.w + er.w; v3 = v3 > 0.f ? v3 : 0.2f * v3;
            s_v[0][tid] = v0; s_v[1][tid] = v1;
            s_v[2][tid] = v2; s_v[3][tid] = v3;
        }
        __syncthreads();

        float m = -1e30f;
        for (int e = lane; e < deg; e += 32) m = fmaxf(m, s_v[h][e]);
        #pragma unroll
        for (int o = 16; o; o >>= 1) m = fmaxf(m, __shfl_xor_sync(0xffffffffu, m, o));

        float z = 0.f;
        for (int e = lane; e < deg; e += 32) {
            float w = __expf(s_v[h][e] - m);
            s_v[h][e] = w;
            z += w;
        }
        #pragma unroll
        for (int o = 16; o; o >>= 1) z += __shfl_xor_sync(0xffffffffu, z, o);
        iz = 1.f / fmaxf(z, 1e-20f);
        __syncwarp();

        int e = 0;
        for (; e + 8 <= deg; e += 8) {
            int ss[8]; float ww[8]; uint2 uu[8];
            #pragma unroll
            for (int q = 0; q < 8; q++) { ss[q] = s_src[e + q]; ww[q] = s_v[h][e + q]; }
            #pragma unroll
            for (int q = 0; q < 8; q++) uu[q] = *(const uint2*)(fbase + (size_t)ss[q] * HDd);
            #pragma unroll
            for (int q = 0; q < 8; q++) {
                float2 a = __half22float2(*(__half2*)&uu[q].x);
                float2 b = __half22float2(*(__half2*)&uu[q].y);
                acc.x += ww[q] * a.x; acc.y += ww[q] * a.y;
                acc.z += ww[q] * b.x; acc.w += ww[q] * b.y;
            }
        }
        for (; e < deg; e++) {
            int s = s_src[e];
            float w = s_v[h][e];
            uint2 u = *(const uint2*)(fbase + (size_t)s * HDd);
            float2 a = __half22float2(*(__half2*)&u.x), b = __half22float2(*(__half2*)&u.y);
            acc.x += w * a.x; acc.y += w * a.y; acc.z += w * b.x; acc.w += w * b.y;
        }
    } else {
        float ern = g_er[n * 4 + h];
        float m = -1e30f, z = 0.f;
        for (int e = beg + lane; e < end; e += 32) {
            int s = g_csrsrc[e];
            float v = g_el[s * 4 + h] + ern;
            v = v > 0.f ? v : 0.2f * v;
            float M = fmaxf(m, v);
            z = z * __expf(m - M) + __expf(v - M);
            m = M;
        }
        #pragma unroll
        for (int o = 16; o; o >>= 1) {
            float mo = __shfl_xor_sync(0xffffffffu, m, o);
            float zo = __shfl_xor_sync(0xffffffffu, z, o);
            float M = fmaxf(m, mo);
            z = z * __expf(m - M) + zo * __expf(mo - M);
            m = M;
        }
        iz = 1.f / fmaxf(z, 1e-20f);
        for (int e = beg; e < end; e++) {
            int s = g_csrsrc[e];
            float v = g_el[s * 4 + h] + ern;
            v = v > 0.f ? v : 0.2f * v;
            float w = __expf(v - m);
            uint2 u = *(const uint2*)(fbase + (size_t)s * HDd);
            float2 a = __half22float2(*(__half2*)&u.x), b = __half22float2(*(__half2*)&u.y);
            acc.x += w * a.x; acc.y += w * a.y; acc.z += w * b.x; acc.w += w * b.y;
        }
    }

    size_t off = (size_t)n * HDd + h * Dd + lane * 4;
    uint2 ru = *(const uint2*)(g_resR + off);
    float2 ra = __half22float2(*(__half2*)&ru.x), rb = __half22float2(*(__half2*)&ru.y);
    float4 bg = *(const float4*)(bgat + h * Dd + lane * 4);
    float4 o;
    o.x = acc.x * iz + ra.x + bg.x;
    o.y = acc.y * iz + ra.y + bg.y;
    o.z = acc.z * iz + rb.x + bg.z;
    o.w = acc.w * iz + rb.y + bg.w;
    o.x = o.x > 0.f ? o.x : 0.01f * o.x;
    o.y = o.y > 0.f ? o.y : 0.01f * o.y;
    o.z = o.z > 0.f ? o.z : 0.01f * o.z;
    o.w = o.w > 0.f ? o.w : 0.01f * o.w;
    uint2 u = pack_h4(o.x, o.y, o.z, o.w);
    *(uint2*)(g_resH + off) = u;
}

// ---------------- launch ----------------
extern "C" void kernel_launch(void* const* d_in, const int* in_sizes, int n_in,
                              void* d_out, int out_size)
{
    const float* features = (const float*)d_in[0];
    const int*   src      = (const int*)  d_in[1];
    const int*   dst      = (const int*)  d_in[2];
    const float* W_fc     = (const float*)d_in[3];
    const float* attn_l   = (const float*)d_in[4];
    const float* attn_r   = (const float*)d_in[5];
    const float* W_res    = (const float*)d_in[6];
    const float* b_gat    = (const float*)d_in[7];
    const float* W_nrm    = (const float*)d_in[8];
    const float* b_nrm    = (const float*)d_in[9];
    const float* ln_g     = (const float*)d_in[10];
    const float* ln_b     = (const float*)d_in[11];
    float* out = (float*)d_out;

    __half *xh0, *xhA, *xhB, *wh, *resH;
    cudaGetSymbolAddress((void**)&xh0,  g_xh0);
    cudaGetSymbolAddress((void**)&xhA,  g_xhA);
    cudaGetSymbolAddress((void**)&xhB,  g_xhB);
    cudaGetSymbolAddress((void**)&wh,   g_wh);
    cudaGetSymbolAddress((void**)&resH, g_resH);

    static int smemSet = 0;
    if (!smemSet) {
        cudaFuncSetAttribute(gemm_h<Dd, HDd / 128>,
                             cudaFuncAttributeMaxDynamicSharedMemorySize, SMBYTES_H);
        smemSet = 1;
    }

    // preamble (vectorized fp16 convert + zero), count, scan -> gemm_h is launch #4
    k_pre<<<(NFEAT / 4 + 255) / 256, 256>>>(W_fc, W_res, W_nrm, features);
    k_count<<<(Ee + 255) / 256, 256>>>(dst);
    k_scan<<<1, 1024>>>();

    const int gy = (Nn + 127) / 128;   // 391
    const int gln = (Nn + 63) / 64;    // 782

    const __half* xin = xh0;
    for (int l = 0; l < Ll; l++) {
        const __half* Wf = wh + (size_t)l * WSZ;
        const __half* Wr = wh + (size_t)(Ll + l) * WSZ;
        const __half* Wn = wh + (size_t)(2 * Ll + l) * WSZ;

        // fused: featH(fp16) + el/er = xin@Wf ; resR(fp16) = xin@Wr
        dim3 g1(2 * (HDd / 128), gy);
        gemm_h<Dd, HDd / 128><<<g1, 256, SMBYTES_H>>>(
            xin, Wf, Wr, Nn, attn_l + l * Hh * Dd, attn_r + l * Hh * Dd);

        if (l == 0) k_fill<<<(Ee + 255) / 256, 256>>>(src, dst);

        k_agg<<<Nn, 128>>>(b_gat + l * HDd);

        // xout = layernorm(resH @ Wn + b_nrm), fused LN epilogue, 64-row tiles
        if (l == Ll - 1) {
            gemm_ln<HDd><<<gln, 256>>>(
                resH, Wn, out, nullptr, Nn,
                b_nrm + l * Dd, ln_g + l * Dd, ln_b + l * Dd, 0);
        } else {
            __half* xout = (l & 1) ? xhB : xhA;
            gemm_ln<HDd><<<gln, 256>>>(
                resH, Wn, nullptr, xout, Nn,
                b_nrm + l * Dd, ln_g + l * Dd, ln_b + l * Dd, 1);
            xin = xout;
        }
    }
}